// round 4
// baseline (speedup 1.0000x reference)
#include <cuda_runtime.h>
#include <cuda_bf16.h>

// Problem constants (fixed by the reference)
#define BATCH 16
#define MCTRL 64
#define NCTRL 64
#define DEG   3
#define LKNOT 68                // M + P + 1
#define NSPAN (LKNOT - 2*DEG)   // 62 candidate spans
#define OUTU  256
#define OUTV  256
#define U_PER 8                 // u samples per block

// Fully fused kernel. Grid: (OUTU/U_PER, BATCH) = (32,16) x 256 threads.
//
//   1. Load this batch's 68 knots, 3-warp shfl inclusive scan, normalize
//      -> K[0..67] in smem. (Nu == Nv and uspan == vspan: the reference
//      builds V from knot_u, and u/v linspaces + degrees are identical.)
//   2. Thread t computes the basis for sample t: span via 6-step binary
//      search (the reference predicate (tv - K[s+3]) > 1e-8 is prefix-true
//      in s because K is monotone and fp subtract preserves monotonicity;
//      we probe the identical fp expression, so the result is bit-equal to
//      the reference argmin-with-first-tie), then Cox-de Boor deg 3.
//      Basis stays in registers for Stage B; only the block's 8 u-samples
//      publish theirs to smem for Stage A.
//   3. Stage A: fold nu into per-u temp rows
//      stmp[up][n] = sum_l nu[l] * ctrl[su+l][n]  (coalesced LDG.128).
//   4. Stage B: per-thread v contraction: 4 LDS.128 + 12 FMA per point.
__global__ void __launch_bounds__(256) surf_kernel(const float* __restrict__ ctrl,
                                                   const float* __restrict__ knot_u,
                                                   float* __restrict__ out) {
    const int u0 = blockIdx.x * U_PER;
    const int b  = blockIdx.y;
    const int t  = threadIdx.x;

    __shared__ float  sc[LKNOT];          // raw cumsum workspace
    __shared__ float  stot[3];            // per-warp scan totals
    __shared__ float  K[LKNOT];           // normalized knots
    __shared__ float4 sbu[U_PER];         // basis for this block's u samples
    __shared__ int    ssu[U_PER];         // span-base for this block's u samples
    __shared__ float4 stmp[U_PER][NCTRL]; // u-folded rows (8 KB)

    // ---- 1. knots + scan + normalize -------------------------------------
    if (t < LKNOT) sc[t] = knot_u[b * LKNOT + t];
    __syncthreads();

    if (t < 96) {  // warps 0..2 cover 68 elements
        const int lane = t & 31;
        float v = (t < LKNOT) ? sc[t] : 0.f;
        #pragma unroll
        for (int off = 1; off < 32; off <<= 1) {
            const float n = __shfl_up_sync(0xffffffffu, v, off);
            if (lane >= off) v += n;
        }
        if (t < LKNOT) sc[t] = v;
        if (lane == 31) stot[t >> 5] = v;
    }
    __syncthreads();

    if (t < LKNOT) {
        float v = sc[t];
        if (t >= 32) v += stot[0];
        if (t >= 64) v += stot[1];
        const float c0    = sc[0];
        const float clast = sc[LKNOT - 1] + stot[0] + stot[1];
        K[t] = (v - c0) / (clast - c0);
    }
    __syncthreads();

    // ---- 2. per-sample basis (registers) ----------------------------------
    // jnp.linspace(1e-5, 1-1e-5, 256): start + i*step, endpoint exact.
    const float start = 1e-5f;
    const float stop  = 1.0f - 1e-5f;
    const float step  = (stop - start) / (float)(OUTU - 1);
    float tv = start + (float)t * step;
    if (t == OUTU - 1) tv = stop;

    // Binary search for cnt = #{ s : (tv - K[s+DEG]) > 1e-8 } (prefix-true).
    int cnt = 0;
    #pragma unroll
    for (int s = 32; s; s >>= 1) {
        const int ns = cnt + s;
        if (ns <= NSPAN && ((tv - K[ns - 1 + DEG]) > 1e-8f)) cnt = ns;
    }
    const int span = DEG + cnt - 1;

    // Cox-de Boor (mirrors the reference arithmetic, including the
    // (K1 - t) + (t - K2) denominator form).
    float Nb[DEG + 1];
    Nb[0] = 1.f;
    #pragma unroll
    for (int k = 1; k <= DEG; k++) {
        float saved = 0.f;
        #pragma unroll
        for (int r = 0; r < k; r++) {
            const float K1 = K[span + r + 1];
            const float K2 = K[span + 1 - k + r];
            const float denom = (K1 - tv) + (tv - K2);
            const float temp  = Nb[r] / denom;
            Nb[r] = saved + (K1 - tv) * temp;
            saved = (tv - K2) * temp;
        }
        Nb[k] = saved;
    }

    // Publish only this block's u-sample bases to smem.
    {
        const unsigned du = (unsigned)(t - u0);
        if (du < U_PER) {
            sbu[du] = make_float4(Nb[0], Nb[1], Nb[2], Nb[3]);
            ssu[du] = span - DEG;
        }
    }
    __syncthreads();

    // ---- 3. Stage A: u-fold -----------------------------------------------
    #pragma unroll
    for (int task = t; task < U_PER * NCTRL; task += 256) {
        const int up = task >> 6;
        const int n  = task & 63;
        const int su = ssu[up];
        const float4 nu = sbu[up];
        const float4* cp = reinterpret_cast<const float4*>(ctrl)
                         + (size_t)b * MCTRL * NCTRL + n;

        const float4 c0 = cp[(su + 0) * NCTRL];
        const float4 c1 = cp[(su + 1) * NCTRL];
        const float4 c2 = cp[(su + 2) * NCTRL];
        const float4 c3 = cp[(su + 3) * NCTRL];

        float4 r;
        r.x = fmaf(nu.x, c0.x, fmaf(nu.y, c1.x, fmaf(nu.z, c2.x, nu.w * c3.x)));
        r.y = fmaf(nu.x, c0.y, fmaf(nu.y, c1.y, fmaf(nu.z, c2.y, nu.w * c3.y)));
        r.z = fmaf(nu.x, c0.z, fmaf(nu.y, c1.z, fmaf(nu.z, c2.z, nu.w * c3.z)));
        r.w = 0.f;
        stmp[up][n] = r;
    }
    __syncthreads();

    // ---- 4. Stage B: per-v contraction (v == t, basis still in registers) --
    const int   sv = span - DEG;
    const float nv0 = Nb[0], nv1 = Nb[1], nv2 = Nb[2], nv3 = Nb[3];

    float* op = out + (((size_t)b * OUTU + u0) * OUTV + t) * 3;

    #pragma unroll
    for (int up = 0; up < U_PER; up++) {
        const float4 c0 = stmp[up][sv + 0];
        const float4 c1 = stmp[up][sv + 1];
        const float4 c2 = stmp[up][sv + 2];
        const float4 c3 = stmp[up][sv + 3];

        const float ax = fmaf(nv0, c0.x, fmaf(nv1, c1.x, fmaf(nv2, c2.x, nv3 * c3.x)));
        const float ay = fmaf(nv0, c0.y, fmaf(nv1, c1.y, fmaf(nv2, c2.y, nv3 * c3.y)));
        const float az = fmaf(nv0, c0.z, fmaf(nv1, c1.z, fmaf(nv2, c2.z, nv3 * c3.z)));

        float* o = op + (size_t)up * OUTV * 3;
        o[0] = ax;
        o[1] = ay;
        o[2] = az;
    }
}

// ---------------------------------------------------------------------------
// Launch. Inputs per metadata order: ctrl_pts [16,64,64,4] f32,
// knot_u [16,68] f32, knot_v [16,68] f32 (unused — the reference builds both
// directions from knot_u).
// ---------------------------------------------------------------------------
extern "C" void kernel_launch(void* const* d_in, const int* in_sizes, int n_in,
                              void* d_out, int out_size) {
    const float* ctrl   = (const float*)d_in[0];
    const float* knot_u = (const float*)d_in[1];
    float* out = (float*)d_out;

    surf_kernel<<<dim3(OUTU / U_PER, BATCH), 256>>>(ctrl, knot_u, out);
}